// round 12
// baseline (speedup 1.0000x reference)
#include <cuda_runtime.h>
#include <math.h>
#include <stdint.h>

#define N_NODES 20000
#define K_IN    8710
#define H_DIM   128
#define C_DIM   70
#define E_MAX   640000

// ---- scratch (static device globals; no allocation allowed) ----
__device__ float g_h[(size_t)N_NODES * H_DIM];    // x@W1 (raw, pre-bias)
__device__ float g_h1[(size_t)N_NODES * H_DIM];   // relu(agg1 + b1)
__device__ float g_z[(size_t)N_NODES * C_DIM];    // h1@W2
__device__ float g_Wr[(size_t)K_IN * H_DIM];      // W1 pre-rounded to tf32
__device__ int   g_deg[N_NODES];
__device__ float g_dinv[N_NODES];
__device__ int   g_ptr[N_NODES + 1];              // CSR row ptr (by dst)
__device__ int   g_cur[N_NODES];                  // fill cursors
__device__ int2  g_csr[E_MAX];                    // {src, bitcast(norm)}
#define SCAN_B 256
#define SCAN_G ((N_NODES + SCAN_B - 1) / SCAN_B)  // 79
__device__ int   g_bsum[SCAN_G];
__device__ int   g_boff[SCAN_G];

// ---------------------------------------------------------------------------
// degree / normalization / CSR build
// ---------------------------------------------------------------------------
__global__ void k_zero_deg() {
    int i = blockIdx.x * blockDim.x + threadIdx.x;
    if (i < N_NODES) g_deg[i] = 0;
}

__global__ void k_count_deg(const int* __restrict__ edges, int E) {
    int e = blockIdx.x * blockDim.x + threadIdx.x;
    if (e < E) atomicAdd(&g_deg[edges[E + e]], 1);   // dst
}

__global__ void k_dinv() {
    int i = blockIdx.x * blockDim.x + threadIdx.x;
    if (i < N_NODES) g_dinv[i] = rsqrtf((float)(g_deg[i] + 1));  // +1 self loop
}

// scan stage 1: per-block sum of degrees
__global__ __launch_bounds__(SCAN_B) void k_scan1() {
    __shared__ int ws[SCAN_B / 32];
    int i = blockIdx.x * SCAN_B + threadIdx.x;
    int v = (i < N_NODES) ? g_deg[i] : 0;
#pragma unroll
    for (int o = 16; o > 0; o >>= 1) v += __shfl_xor_sync(0xffffffff, v, o);
    if ((threadIdx.x & 31) == 0) ws[threadIdx.x >> 5] = v;
    __syncthreads();
    if (threadIdx.x < SCAN_B / 32) {
        int s = ws[threadIdx.x];
#pragma unroll
        for (int o = SCAN_B / 64; o > 0; o >>= 1)
            s += __shfl_xor_sync(0xffffffff, s, o, SCAN_B / 32);
        if (threadIdx.x == 0) g_bsum[blockIdx.x] = s;
    }
}

// scan stage 2: exclusive scan of the 79 block sums (1 block)
__global__ __launch_bounds__(128) void k_scan2() {
    __shared__ int sh[SCAN_G];
    int t = threadIdx.x;
    if (t < SCAN_G) sh[t] = g_bsum[t];
    __syncthreads();
    if (t == 0) {
        int run = 0;
        for (int b = 0; b < SCAN_G; b++) { g_boff[b] = run; run += sh[b]; }
        g_ptr[N_NODES] = run;
    }
}

// scan stage 3: per-block exclusive scan + offset -> g_ptr / g_cur
__global__ __launch_bounds__(SCAN_B) void k_scan3() {
    __shared__ int sh[SCAN_B];
    int i = blockIdx.x * SCAN_B + threadIdx.x;
    int v = (i < N_NODES) ? g_deg[i] : 0;
    sh[threadIdx.x] = v;
    __syncthreads();
    // Hillis-Steele inclusive scan
    for (int o = 1; o < SCAN_B; o <<= 1) {
        int t = (threadIdx.x >= o) ? sh[threadIdx.x - o] : 0;
        __syncthreads();
        sh[threadIdx.x] += t;
        __syncthreads();
    }
    if (i < N_NODES) {
        int excl = sh[threadIdx.x] - v + g_boff[blockIdx.x];
        g_ptr[i] = excl;
        g_cur[i] = excl;
    }
}

__global__ void k_fill(const int* __restrict__ edges, int E) {
    int e = blockIdx.x * blockDim.x + threadIdx.x;
    if (e >= E) return;
    int s = edges[e];
    int d = edges[E + e];
    int pos = atomicAdd(&g_cur[d], 1);
    g_csr[pos] = make_int2(s, __float_as_int(g_dinv[s] * g_dinv[d]));
}

// ---------------------------------------------------------------------------
// pre-round W1 to tf32 (rna) so GEMM needs no in-loop cvt for B
// ---------------------------------------------------------------------------
__global__ void k_round_w(const float* __restrict__ W1) {
    int i = blockIdx.x * blockDim.x + threadIdx.x;
    if (i < K_IN * H_DIM) {
        unsigned u;
        asm("cvt.rna.tf32.f32 %0, %1;" : "=r"(u) : "f"(W1[i]));
        g_Wr[i] = __uint_as_float(u);
    }
}

// ---------------------------------------------------------------------------
// zero-init g_h rows of the split-K tiles (rows 18944..19999)
// ---------------------------------------------------------------------------
#define SPLIT_ROW0 18944
__global__ void k_zero_tail() {
    int idx = blockIdx.x * blockDim.x + threadIdx.x;   // float4 slots
    int total = (N_NODES - SPLIT_ROW0) * 32;
    if (idx >= total) return;
    *reinterpret_cast<float4*>(g_h + (size_t)SPLIT_ROW0 * H_DIM + idx * 4) =
        make_float4(0.f, 0.f, 0.f, 0.f);
}

// ---------------------------------------------------------------------------
// GEMM1, tf32 HMMA + cp.async 5-stage pipeline, 512 threads = 16 warps (4x4),
// warp tile 32x32. BM=128, BN=128, BK=16.
//   bid 0..147   : full tiles, chunks [0,545), direct-store epilogue
//   bid 148..291 : tiles 148..156 split-K x16, red.add epilogue
// ---------------------------------------------------------------------------
#define NC_CHUNKS ((K_IN + 15) / 16)   // 545
#define G1_STAGES 5
#define G1_BM 128
#define G1_BK 16
#define N_FULL    148
#define N_SPLITS  16
#define A_STRIDE 20
#define B_STRIDE 136
#define A_WORDS (G1_BM * A_STRIDE)                   // 2560
#define STAGE_WORDS (A_WORDS + G1_BK * B_STRIDE)     // 4736
#define G1_SMEM_BYTES (G1_STAGES * STAGE_WORDS * 4)  // 94720
#define TRUNC_COMP 1.00034f

__device__ __forceinline__ unsigned smem_u32(const void* p) {
    unsigned a;
    asm("{ .reg .u64 t; cvta.to.shared.u64 t, %1; cvt.u32.u64 %0, t; }"
        : "=r"(a) : "l"(p));
    return a;
}

__global__ __launch_bounds__(512, 1) void k_gemm1_tc(const float* __restrict__ X) {
    extern __shared__ float sm[];

    const int tid  = threadIdx.x;
    const int warp = tid >> 5;
    const int lane = tid & 31;
    const int gid  = lane >> 2;     // 0..7
    const int tig  = lane & 3;      // 0..3
    const int warp_m = warp >> 2;   // 0..3
    const int warp_n = warp & 3;    // 0..3
    const unsigned sm_base = smem_u32(sm);

    int tile, c0, c_end;
    bool direct;
    if (blockIdx.x < N_FULL) {
        tile = blockIdx.x; c0 = 0; c_end = NC_CHUNKS; direct = true;
    } else {
        int t = blockIdx.x - N_FULL;
        tile = N_FULL + t / N_SPLITS;
        int s = t % N_SPLITS;
        const int base = NC_CHUNKS / N_SPLITS;
        const int rem  = NC_CHUNKS % N_SPLITS;
        c0    = s * base + (s < rem ? s : rem);
        c_end = c0 + base + (s < rem ? 1 : 0);
        direct = false;
    }
    const int m0 = tile * G1_BM;

    float acc[2][4][4];
#pragma unroll
    for (int i = 0; i < 2; i++)
#pragma unroll
        for (int j = 0; j < 4; j++)
#pragma unroll
            for (int t = 0; t < 4; t++) acc[i][j][t] = 0.f;

    // A: 128 rows x 16 k = 1024 float2 slots (2/thread)
    // B: 16 k x 128 n = 512 float4 slots (1/thread)
#define LOAD_STAGE(c)                                                             \
    {                                                                             \
        const int stg = (c) % G1_STAGES;                                          \
        const unsigned a_u = sm_base + stg * (STAGE_WORDS * 4);                   \
        const unsigned b_u = a_u + A_WORDS * 4;                                   \
        const int k0 = (c) * G1_BK;                                               \
        const bool inr = (c) < c_end;                                             \
        _Pragma("unroll")                                                         \
        for (int i = 0; i < 2; i++) {                                             \
            int p = tid + i * 512;                                                \
            int row = p >> 3;                                                     \
            int kp  = (p & 7) * 2;                                                \
            int gm = m0 + row, gk = k0 + kp;                                      \
            int ok = (inr && gm < N_NODES && gk + 1 < K_IN) ? 8 : 0;              \
            int gmc = gm < N_NODES ? gm : N_NODES - 1;                            \
            int gkc = gk + 1 < K_IN ? gk : 0;                                     \
            const float* src = X + (size_t)gmc * K_IN + gkc;                      \
            unsigned dst = a_u + (row * A_STRIDE + kp) * 4;                       \
            asm volatile("cp.async.ca.shared.global [%0], [%1], 8, %2;"           \
                         :: "r"(dst), "l"(src), "r"(ok));                         \
        }                                                                         \
        {                                                                         \
            int kr = tid >> 5;                                                    \
            int nc = (tid & 31) * 4;                                              \
            int gk = k0 + kr;                                                     \
            int ok = (inr && gk < K_IN) ? 16 : 0;                                 \
            int gkc = gk < K_IN ? gk : 0;                                         \
            const float* src = g_Wr + (size_t)gkc * H_DIM + nc;                   \
            unsigned dst = b_u + (kr * B_STRIDE + nc) * 4;                        \
            asm volatile("cp.async.cg.shared.global [%0], [%1], 16, %2;"          \
                         :: "r"(dst), "l"(src), "r"(ok));                         \
        }                                                                         \
        asm volatile("cp.async.commit_group;");                                   \
    }

    LOAD_STAGE(c0);
    LOAD_STAGE(c0 + 1);
    LOAD_STAGE(c0 + 2);
    LOAD_STAGE(c0 + 3);

    for (int c = c0; c < c_end; ++c) {
        asm volatile("cp.async.wait_group %0;" :: "n"(G1_STAGES - 2));
        __syncthreads();

        LOAD_STAGE(c + G1_STAGES - 1);

        const unsigned* As = reinterpret_cast<const unsigned*>(
            sm + (c % G1_STAGES) * STAGE_WORDS);
        const unsigned* Bs = As + A_WORDS;

#pragma unroll
        for (int ks = 0; ks < 2; ks++) {
            const int kb = ks * 8;
            unsigned af[2][4];
#pragma unroll
            for (int mt = 0; mt < 2; mt++) {
                int r = warp_m * 32 + mt * 16 + gid;
                af[mt][0] = As[r * A_STRIDE + kb + tig];
                af[mt][1] = As[(r + 8) * A_STRIDE + kb + tig];
                af[mt][2] = As[r * A_STRIDE + kb + tig + 4];
                af[mt][3] = As[(r + 8) * A_STRIDE + kb + tig + 4];
            }
            unsigned bf[4][2];
#pragma unroll
            for (int nt = 0; nt < 4; nt++) {
                int nb = warp_n * 32 + nt * 8 + gid;
                bf[nt][0] = Bs[(kb + tig) * B_STRIDE + nb];
                bf[nt][1] = Bs[(kb + tig + 4) * B_STRIDE + nb];
            }
#pragma unroll
            for (int mt = 0; mt < 2; mt++)
#pragma unroll
                for (int nt = 0; nt < 4; nt++) {
                    asm volatile(
                        "mma.sync.aligned.m16n8k8.row.col.f32.tf32.tf32.f32 "
                        "{%0,%1,%2,%3}, {%4,%5,%6,%7}, {%8,%9}, {%0,%1,%2,%3};"
                        : "+f"(acc[mt][nt][0]), "+f"(acc[mt][nt][1]),
                          "+f"(acc[mt][nt][2]), "+f"(acc[mt][nt][3])
                        : "r"(af[mt][0]), "r"(af[mt][1]), "r"(af[mt][2]), "r"(af[mt][3]),
                          "r"(bf[nt][0]), "r"(bf[nt][1]));
                }
        }
    }
#undef LOAD_STAGE

    // epilogue: truncation compensation, write h only (agg is pulled later)
#pragma unroll
    for (int mt = 0; mt < 2; mt++) {
        int r0 = m0 + warp_m * 32 + mt * 16 + gid;
        int r1 = r0 + 8;
#pragma unroll
        for (int nt = 0; nt < 4; nt++) {
            int col = warp_n * 32 + nt * 8 + tig * 2;
            float h0 = acc[mt][nt][0] * TRUNC_COMP;
            float h1 = acc[mt][nt][1] * TRUNC_COMP;
            float h2 = acc[mt][nt][2] * TRUNC_COMP;
            float h3 = acc[mt][nt][3] * TRUNC_COMP;
            if (direct) {
                if (r0 < N_NODES)
                    *reinterpret_cast<float2*>(g_h + (size_t)r0 * H_DIM + col) =
                        make_float2(h0, h1);
                if (r1 < N_NODES)
                    *reinterpret_cast<float2*>(g_h + (size_t)r1 * H_DIM + col) =
                        make_float2(h2, h3);
            } else {
                if (r0 < N_NODES)
                    asm volatile("red.global.add.v2.f32 [%0], {%1,%2};"
                                 :: "l"(g_h + (size_t)r0 * H_DIM + col),
                                    "f"(h0), "f"(h1) : "memory");
                if (r1 < N_NODES)
                    asm volatile("red.global.add.v2.f32 [%0], {%1,%2};"
                                 :: "l"(g_h + (size_t)r1 * H_DIM + col),
                                    "f"(h2), "f"(h3) : "memory");
            }
        }
    }
}

// ---------------------------------------------------------------------------
// layer-1 pull aggregation: h1[n] = relu(b1 + dinv^2*h[n] + sum norm*h[src])
// ---------------------------------------------------------------------------
__global__ __launch_bounds__(256) void k_agg1(const float* __restrict__ b1) {
    int warp = threadIdx.x >> 5, lane = threadIdx.x & 31;
    int n = blockIdx.x * 8 + warp;
    if (n >= N_NODES) return;

    float dv = g_dinv[n];
    float self = dv * dv;
    const float4* hn = reinterpret_cast<const float4*>(g_h + (size_t)n * H_DIM);
    float4 v = __ldg(hn + lane);
    float4 acc = make_float4(v.x * self, v.y * self, v.z * self, v.w * self);

    int j  = g_ptr[n];
    int p1 = g_ptr[n + 1];
    int2 en;
    if (j < p1) en = __ldg(&g_csr[j]);
    while (j < p1) {
        int2 cur = en;
        if (j + 1 < p1) en = __ldg(&g_csr[j + 1]);
        float nrm = __int_as_float(cur.y);
        float4 w = __ldg(reinterpret_cast<const float4*>(
                             g_h + (size_t)cur.x * H_DIM) + lane);
        acc.x += w.x * nrm; acc.y += w.y * nrm;
        acc.z += w.z * nrm; acc.w += w.w * nrm;
        ++j;
    }

    float4 b = __ldg(reinterpret_cast<const float4*>(b1) + lane);
    acc.x = fmaxf(acc.x + b.x, 0.f);
    acc.y = fmaxf(acc.y + b.y, 0.f);
    acc.z = fmaxf(acc.z + b.z, 0.f);
    acc.w = fmaxf(acc.w + b.w, 0.f);
    reinterpret_cast<float4*>(g_h1 + (size_t)n * H_DIM)[lane] = acc;
}

// ---------------------------------------------------------------------------
// GEMM2: z = h1 @ W2   [20000 x 128] @ [128 x 70] — warp per row
// ---------------------------------------------------------------------------
__global__ __launch_bounds__(256) void k_gemm2(const float* __restrict__ W2) {
    __shared__ float W2s[H_DIM * C_DIM];
    int tid = threadIdx.x;
    for (int i = tid; i < H_DIM * C_DIM; i += 256) W2s[i] = W2[i];
    __syncthreads();

    int warp = tid >> 5, lane = tid & 31;
    int n = blockIdx.x * 8 + warp;
    if (n >= N_NODES) return;
    const float* hr = g_h1 + (size_t)n * H_DIM;

    float a0 = 0.f, a1 = 0.f, a2 = 0.f;
#pragma unroll 4
    for (int k = 0; k < H_DIM; k++) {
        float hv = __ldg(hr + k);
        const float* wr = W2s + k * C_DIM;
        a0 += hv * wr[lane];
        a1 += hv * wr[lane + 32];
        if (lane < C_DIM - 64) a2 += hv * wr[lane + 64];
    }
    float* zr = g_z + (size_t)n * C_DIM;
    zr[lane]      = a0;
    zr[lane + 32] = a1;
    if (lane < C_DIM - 64) zr[lane + 64] = a2;
}

// ---------------------------------------------------------------------------
// layer-2 pull aggregation + bias + softmax -> out
// ---------------------------------------------------------------------------
__global__ __launch_bounds__(256) void k_agg2(const float* __restrict__ b2,
                                              float* __restrict__ out) {
    int warp = threadIdx.x >> 5, lane = threadIdx.x & 31;
    int n = blockIdx.x * 8 + warp;
    if (n >= N_NODES) return;
    const bool xtra = lane < 3;

    float dv = g_dinv[n];
    float self = dv * dv;
    const float* zn = g_z + (size_t)n * C_DIM;
    float2 a = *reinterpret_cast<const float2*>(zn + 2 * lane);
    a.x *= self; a.y *= self;
    float2 bacc = make_float2(0.f, 0.f);
    if (xtra) {
        float2 t = *reinterpret_cast<const float2*>(zn + 64 + 2 * lane);
        bacc.x = t.x * self; bacc.y = t.y * self;
    }

    int j  = g_ptr[n];
    int p1 = g_ptr[n + 1];
    int2 en;
    if (j < p1) en = __ldg(&g_csr[j]);
    while (j < p1) {
        int2 cur = en;
        if (j + 1 < p1) en = __ldg(&g_csr[j + 1]);
        float nrm = __int_as_float(cur.y);
        const float* zs = g_z + (size_t)cur.x * C_DIM;
        float2 v = __ldg(reinterpret_cast<const float2*>(zs + 2 * lane));
        a.x += v.x * nrm; a.y += v.y * nrm;
        if (xtra) {
            float2 t = __ldg(reinterpret_cast<const float2*>(zs + 64 + 2 * lane));
            bacc.x += t.x * nrm; bacc.y += t.y * nrm;
        }
        ++j;
    }

    a.x += b2[2 * lane]; a.y += b2[2 * lane + 1];
    if (xtra) { bacc.x += b2[64 + 2 * lane]; bacc.y += b2[65 + 2 * lane]; }

    float m = fmaxf(a.x, a.y);
    if (xtra) m = fmaxf(m, fmaxf(bacc.x, bacc.y));
#pragma unroll
    for (int o = 16; o > 0; o >>= 1) m = fmaxf(m, __shfl_xor_sync(0xffffffff, m, o));

    float e0 = expf(a.x - m), e1 = expf(a.y - m);
    float e2 = 0.f, e3 = 0.f;
    if (xtra) { e2 = expf(bacc.x - m); e3 = expf(bacc.y - m); }
    float s = e0 + e1 + e2 + e3;
#pragma unroll
    for (int o = 16; o > 0; o >>= 1) s += __shfl_xor_sync(0xffffffff, s, o);
    float inv = 1.f / s;

    float* orow = out + (size_t)n * C_DIM;
    *reinterpret_cast<float2*>(orow + 2 * lane) = make_float2(e0 * inv, e1 * inv);
    if (xtra)
        *reinterpret_cast<float2*>(orow + 64 + 2 * lane) =
            make_float2(e2 * inv, e3 * inv);
}

// ---------------------------------------------------------------------------
extern "C" void kernel_launch(void* const* d_in, const int* in_sizes, int n_in,
                              void* d_out, int out_size) {
    const float* x  = (const float*)d_in[0];
    const int* edges = (const int*)d_in[1];
    const float* W1 = (const float*)d_in[2];
    const float* b1 = (const float*)d_in[3];
    const float* W2 = (const float*)d_in[4];
    const float* b2 = (const float*)d_in[5];
    float* out = (float*)d_out;
    const int E = in_sizes[1] / 2;

    cudaFuncSetAttribute(k_gemm1_tc, cudaFuncAttributeMaxDynamicSharedMemorySize,
                         G1_SMEM_BYTES);

    // degree / dinv / CSR / weight prep
    k_zero_deg<<<(N_NODES + 255) / 256, 256>>>();
    k_count_deg<<<(E + 255) / 256, 256>>>(edges, E);
    k_dinv<<<(N_NODES + 255) / 256, 256>>>();
    k_scan1<<<SCAN_G, SCAN_B>>>();
    k_scan2<<<1, 128>>>();
    k_scan3<<<SCAN_G, SCAN_B>>>();
    k_fill<<<(E + 255) / 256, 256>>>(edges, E);
    k_round_w<<<(K_IN * H_DIM + 255) / 256, 256>>>(W1);
    k_zero_tail<<<((N_NODES - SPLIT_ROW0) * 32 + 255) / 256, 256>>>();

    // layer 1
    k_gemm1_tc<<<N_FULL + (157 - N_FULL) * N_SPLITS, 512, G1_SMEM_BYTES>>>(x);
    k_agg1<<<(N_NODES + 7) / 8, 256>>>(b1);

    // layer 2
    k_gemm2<<<(N_NODES + 7) / 8, 256>>>(W2);
    k_agg2<<<(N_NODES + 7) / 8, 256>>>(b2, out);
}

// round 13
// speedup vs baseline: 1.1502x; 1.1502x over previous
#include <cuda_runtime.h>
#include <math.h>
#include <stdint.h>

#define N_NODES 20000
#define K_IN    8710
#define H_DIM   128
#define C_DIM   70
#define E_MAX   640000

// ---- scratch (static device globals; no allocation allowed) ----
__device__ float g_h[(size_t)N_NODES * H_DIM];    // x@W1 (raw, pre-bias)
__device__ float g_h1[(size_t)N_NODES * H_DIM];   // relu(agg1 + b1)
__device__ float g_z[(size_t)N_NODES * C_DIM];    // h1@W2
__device__ float g_Wr[(size_t)K_IN * H_DIM];      // W1 pre-rounded to tf32
__device__ int   g_deg[N_NODES];
__device__ float g_dinv[N_NODES];
__device__ int   g_ptr[N_NODES + 1];              // CSR row ptr (by dst)
__device__ int   g_cur[N_NODES];                  // fill cursors
__device__ int2  g_csr[E_MAX];                    // {src, bitcast(norm)}
#define SCAN_B 256
#define SCAN_G ((N_NODES + SCAN_B - 1) / SCAN_B)  // 79
__device__ int   g_bsum[SCAN_G];
__device__ int   g_boff[SCAN_G];

// ---------------------------------------------------------------------------
// degree / normalization / CSR build
// ---------------------------------------------------------------------------
__global__ void k_zero_deg() {
    int i = blockIdx.x * blockDim.x + threadIdx.x;
    if (i < N_NODES) g_deg[i] = 0;
}

__global__ void k_count_deg(const int* __restrict__ edges, int E) {
    int e = blockIdx.x * blockDim.x + threadIdx.x;
    if (e < E) atomicAdd(&g_deg[edges[E + e]], 1);   // dst
}

__global__ void k_dinv() {
    int i = blockIdx.x * blockDim.x + threadIdx.x;
    if (i < N_NODES) g_dinv[i] = rsqrtf((float)(g_deg[i] + 1));  // +1 self loop
}

// scan stage 1: per-block sum of degrees
__global__ __launch_bounds__(SCAN_B) void k_scan1() {
    __shared__ int ws[SCAN_B / 32];
    int i = blockIdx.x * SCAN_B + threadIdx.x;
    int v = (i < N_NODES) ? g_deg[i] : 0;
#pragma unroll
    for (int o = 16; o > 0; o >>= 1) v += __shfl_xor_sync(0xffffffff, v, o);
    if ((threadIdx.x & 31) == 0) ws[threadIdx.x >> 5] = v;
    __syncthreads();
    if (threadIdx.x < SCAN_B / 32) {
        int s = ws[threadIdx.x];
#pragma unroll
        for (int o = SCAN_B / 64; o > 0; o >>= 1)
            s += __shfl_xor_sync(0xffffffff, s, o, SCAN_B / 32);
        if (threadIdx.x == 0) g_bsum[blockIdx.x] = s;
    }
}

// scan stage 2: exclusive scan of the 79 block sums (1 block)
__global__ __launch_bounds__(128) void k_scan2() {
    __shared__ int sh[SCAN_G];
    int t = threadIdx.x;
    if (t < SCAN_G) sh[t] = g_bsum[t];
    __syncthreads();
    if (t == 0) {
        int run = 0;
        for (int b = 0; b < SCAN_G; b++) { g_boff[b] = run; run += sh[b]; }
        g_ptr[N_NODES] = run;
    }
}

// scan stage 3: per-block exclusive scan + offset -> g_ptr / g_cur
__global__ __launch_bounds__(SCAN_B) void k_scan3() {
    __shared__ int sh[SCAN_B];
    int i = blockIdx.x * SCAN_B + threadIdx.x;
    int v = (i < N_NODES) ? g_deg[i] : 0;
    sh[threadIdx.x] = v;
    __syncthreads();
    for (int o = 1; o < SCAN_B; o <<= 1) {
        int t = (threadIdx.x >= o) ? sh[threadIdx.x - o] : 0;
        __syncthreads();
        sh[threadIdx.x] += t;
        __syncthreads();
    }
    if (i < N_NODES) {
        int excl = sh[threadIdx.x] - v + g_boff[blockIdx.x];
        g_ptr[i] = excl;
        g_cur[i] = excl;
    }
}

__global__ void k_fill(const int* __restrict__ edges, int E) {
    int e = blockIdx.x * blockDim.x + threadIdx.x;
    if (e >= E) return;
    int s = edges[e];
    int d = edges[E + e];
    int pos = atomicAdd(&g_cur[d], 1);
    g_csr[pos] = make_int2(s, __float_as_int(g_dinv[s] * g_dinv[d]));
}

// ---------------------------------------------------------------------------
// pre-round W1 to tf32 (rna) so GEMM needs no in-loop cvt for B
// ---------------------------------------------------------------------------
__global__ void k_round_w(const float* __restrict__ W1) {
    int i = blockIdx.x * blockDim.x + threadIdx.x;
    if (i < K_IN * H_DIM) {
        unsigned u;
        asm("cvt.rna.tf32.f32 %0, %1;" : "=r"(u) : "f"(W1[i]));
        g_Wr[i] = __uint_as_float(u);
    }
}

// ---------------------------------------------------------------------------
// zero-init g_h rows of the split-K tiles (rows 18944..19999)
// ---------------------------------------------------------------------------
#define SPLIT_ROW0 18944
__global__ void k_zero_tail() {
    int idx = blockIdx.x * blockDim.x + threadIdx.x;   // float4 slots
    int total = (N_NODES - SPLIT_ROW0) * 32;
    if (idx >= total) return;
    *reinterpret_cast<float4*>(g_h + (size_t)SPLIT_ROW0 * H_DIM + idx * 4) =
        make_float4(0.f, 0.f, 0.f, 0.f);
}

// ---------------------------------------------------------------------------
// GEMM1, tf32 HMMA + cp.async 4-stage pipeline (known-good R8 inner loop)
//   bid 0..147   : full tiles, chunks [0,545), direct-store epilogue
//   bid 148..291 : tiles 148..156 split-K x16, red.add epilogue
// BM=128, BN=128, BK=16, 256 threads = 8 warps (4m x 2n), warp tile 32x64
// ---------------------------------------------------------------------------
#define NC_CHUNKS ((K_IN + 15) / 16)   // 545
#define G1_STAGES 4
#define G1_BM 128
#define G1_BK 16
#define N_FULL    148
#define N_SPLITS  16
#define A_STRIDE 20
#define B_STRIDE 136
#define A_WORDS (G1_BM * A_STRIDE)                   // 2560
#define STAGE_WORDS (A_WORDS + G1_BK * B_STRIDE)     // 4736
#define G1_SMEM_BYTES (G1_STAGES * STAGE_WORDS * 4)  // 75776
#define TRUNC_COMP 1.00034f

__device__ __forceinline__ unsigned smem_u32(const void* p) {
    unsigned a;
    asm("{ .reg .u64 t; cvta.to.shared.u64 t, %1; cvt.u32.u64 %0, t; }"
        : "=r"(a) : "l"(p));
    return a;
}

__global__ __launch_bounds__(256, 2) void k_gemm1_tc(const float* __restrict__ X) {
    extern __shared__ float sm[];

    const int tid  = threadIdx.x;
    const int warp = tid >> 5;
    const int lane = tid & 31;
    const int gid  = lane >> 2;
    const int tig  = lane & 3;
    const int warp_m = warp >> 1;
    const int warp_n = warp & 1;
    const unsigned sm_base = smem_u32(sm);

    int tile, c0, c_end;
    bool direct;
    if (blockIdx.x < N_FULL) {
        tile = blockIdx.x; c0 = 0; c_end = NC_CHUNKS; direct = true;
    } else {
        int t = blockIdx.x - N_FULL;
        tile = N_FULL + t / N_SPLITS;
        int s = t % N_SPLITS;
        const int base = NC_CHUNKS / N_SPLITS;
        const int rem  = NC_CHUNKS % N_SPLITS;
        c0    = s * base + (s < rem ? s : rem);
        c_end = c0 + base + (s < rem ? 1 : 0);
        direct = false;
    }
    const int m0 = tile * G1_BM;

    float acc[2][8][4];
#pragma unroll
    for (int i = 0; i < 2; i++)
#pragma unroll
        for (int j = 0; j < 8; j++)
#pragma unroll
            for (int t = 0; t < 4; t++) acc[i][j][t] = 0.f;

#define LOAD_STAGE(c)                                                             \
    {                                                                             \
        const int stg = (c) % G1_STAGES;                                          \
        const unsigned a_u = sm_base + stg * (STAGE_WORDS * 4);                   \
        const unsigned b_u = a_u + A_WORDS * 4;                                   \
        const int k0 = (c) * G1_BK;                                               \
        const bool inr = (c) < c_end;                                             \
        _Pragma("unroll")                                                         \
        for (int i = 0; i < 4; i++) {                                             \
            int p = tid + i * 256;                                                \
            int row = p >> 3;                                                     \
            int kp  = (p & 7) * 2;                                                \
            int gm = m0 + row, gk = k0 + kp;                                      \
            int ok = (inr && gm < N_NODES && gk + 1 < K_IN) ? 8 : 0;              \
            int gmc = gm < N_NODES ? gm : N_NODES - 1;                            \
            int gkc = gk + 1 < K_IN ? gk : 0;                                     \
            const float* src = X + (size_t)gmc * K_IN + gkc;                      \
            unsigned dst = a_u + (row * A_STRIDE + kp) * 4;                       \
            asm volatile("cp.async.ca.shared.global [%0], [%1], 8, %2;"           \
                         :: "r"(dst), "l"(src), "r"(ok));                         \
        }                                                                         \
        _Pragma("unroll")                                                         \
        for (int i = 0; i < 2; i++) {                                             \
            int q = tid + i * 256;                                                \
            int kr = q >> 5;                                                      \
            int nc = (q & 31) * 4;                                                \
            int gk = k0 + kr;                                                     \
            int ok = (inr && gk < K_IN) ? 16 : 0;                                 \
            int gkc = gk < K_IN ? gk : 0;                                         \
            const float* src = g_Wr + (size_t)gkc * H_DIM + nc;                   \
            unsigned dst = b_u + (kr * B_STRIDE + nc) * 4;                        \
            asm volatile("cp.async.cg.shared.global [%0], [%1], 16, %2;"          \
                         :: "r"(dst), "l"(src), "r"(ok));                         \
        }                                                                         \
        asm volatile("cp.async.commit_group;");                                   \
    }

    LOAD_STAGE(c0);
    LOAD_STAGE(c0 + 1);
    LOAD_STAGE(c0 + 2);

    for (int c = c0; c < c_end; ++c) {
        asm volatile("cp.async.wait_group %0;" :: "n"(G1_STAGES - 2));
        __syncthreads();

        LOAD_STAGE(c + G1_STAGES - 1);

        const unsigned* As = reinterpret_cast<const unsigned*>(
            sm + (c % G1_STAGES) * STAGE_WORDS);
        const unsigned* Bs = As + A_WORDS;

#pragma unroll
        for (int ks = 0; ks < 2; ks++) {
            const int kb = ks * 8;
            unsigned af[2][4];
#pragma unroll
            for (int mt = 0; mt < 2; mt++) {
                int r = warp_m * 32 + mt * 16 + gid;
                af[mt][0] = As[r * A_STRIDE + kb + tig];
                af[mt][1] = As[(r + 8) * A_STRIDE + kb + tig];
                af[mt][2] = As[r * A_STRIDE + kb + tig + 4];
                af[mt][3] = As[(r + 8) * A_STRIDE + kb + tig + 4];
            }
            unsigned bf[8][2];
#pragma unroll
            for (int nt = 0; nt < 8; nt++) {
                int nb = warp_n * 64 + nt * 8 + gid;
                bf[nt][0] = Bs[(kb + tig) * B_STRIDE + nb];
                bf[nt][1] = Bs[(kb + tig + 4) * B_STRIDE + nb];
            }
#pragma unroll
            for (int mt = 0; mt < 2; mt++)
#pragma unroll
                for (int nt = 0; nt < 8; nt++) {
                    asm volatile(
                        "mma.sync.aligned.m16n8k8.row.col.f32.tf32.tf32.f32 "
                        "{%0,%1,%2,%3}, {%4,%5,%6,%7}, {%8,%9}, {%0,%1,%2,%3};"
                        : "+f"(acc[mt][nt][0]), "+f"(acc[mt][nt][1]),
                          "+f"(acc[mt][nt][2]), "+f"(acc[mt][nt][3])
                        : "r"(af[mt][0]), "r"(af[mt][1]), "r"(af[mt][2]), "r"(af[mt][3]),
                          "r"(bf[nt][0]), "r"(bf[nt][1]));
                }
        }
    }
#undef LOAD_STAGE

    // epilogue: truncation compensation, write h only (agg is pulled later)
#pragma unroll
    for (int mt = 0; mt < 2; mt++) {
        int r0 = m0 + warp_m * 32 + mt * 16 + gid;
        int r1 = r0 + 8;
#pragma unroll
        for (int nt = 0; nt < 8; nt++) {
            int col = warp_n * 64 + nt * 8 + tig * 2;
            float h0 = acc[mt][nt][0] * TRUNC_COMP;
            float h1 = acc[mt][nt][1] * TRUNC_COMP;
            float h2 = acc[mt][nt][2] * TRUNC_COMP;
            float h3 = acc[mt][nt][3] * TRUNC_COMP;
            if (direct) {
                if (r0 < N_NODES)
                    *reinterpret_cast<float2*>(g_h + (size_t)r0 * H_DIM + col) =
                        make_float2(h0, h1);
                if (r1 < N_NODES)
                    *reinterpret_cast<float2*>(g_h + (size_t)r1 * H_DIM + col) =
                        make_float2(h2, h3);
            } else {
                if (r0 < N_NODES)
                    asm volatile("red.global.add.v2.f32 [%0], {%1,%2};"
                                 :: "l"(g_h + (size_t)r0 * H_DIM + col),
                                    "f"(h0), "f"(h1) : "memory");
                if (r1 < N_NODES)
                    asm volatile("red.global.add.v2.f32 [%0], {%1,%2};"
                                 :: "l"(g_h + (size_t)r1 * H_DIM + col),
                                    "f"(h2), "f"(h3) : "memory");
            }
        }
    }
}

// ---------------------------------------------------------------------------
// layer-1 pull aggregation: h1[n] = relu(b1 + dinv^2*h[n] + sum norm*h[src])
// ---------------------------------------------------------------------------
__global__ __launch_bounds__(256) void k_agg1(const float* __restrict__ b1) {
    int warp = threadIdx.x >> 5, lane = threadIdx.x & 31;
    int n = blockIdx.x * 8 + warp;
    if (n >= N_NODES) return;

    float dv = g_dinv[n];
    float self = dv * dv;
    const float4* hn = reinterpret_cast<const float4*>(g_h + (size_t)n * H_DIM);
    float4 v = __ldg(hn + lane);
    float4 acc = make_float4(v.x * self, v.y * self, v.z * self, v.w * self);

    int j  = g_ptr[n];
    int p1 = g_ptr[n + 1];
    int2 en;
    if (j < p1) en = __ldg(&g_csr[j]);
    while (j < p1) {
        int2 cur = en;
        if (j + 1 < p1) en = __ldg(&g_csr[j + 1]);
        float nrm = __int_as_float(cur.y);
        float4 w = __ldg(reinterpret_cast<const float4*>(
                             g_h + (size_t)cur.x * H_DIM) + lane);
        acc.x += w.x * nrm; acc.y += w.y * nrm;
        acc.z += w.z * nrm; acc.w += w.w * nrm;
        ++j;
    }

    float4 b = __ldg(reinterpret_cast<const float4*>(b1) + lane);
    acc.x = fmaxf(acc.x + b.x, 0.f);
    acc.y = fmaxf(acc.y + b.y, 0.f);
    acc.z = fmaxf(acc.z + b.z, 0.f);
    acc.w = fmaxf(acc.w + b.w, 0.f);
    reinterpret_cast<float4*>(g_h1 + (size_t)n * H_DIM)[lane] = acc;
}

// ---------------------------------------------------------------------------
// GEMM2: z = h1 @ W2   [20000 x 128] @ [128 x 70] — warp per row
// ---------------------------------------------------------------------------
__global__ __launch_bounds__(256) void k_gemm2(const float* __restrict__ W2) {
    __shared__ float W2s[H_DIM * C_DIM];
    int tid = threadIdx.x;
    for (int i = tid; i < H_DIM * C_DIM; i += 256) W2s[i] = W2[i];
    __syncthreads();

    int warp = tid >> 5, lane = tid & 31;
    int n = blockIdx.x * 8 + warp;
    if (n >= N_NODES) return;
    const float* hr = g_h1 + (size_t)n * H_DIM;

    float a0 = 0.f, a1 = 0.f, a2 = 0.f;
#pragma unroll 4
    for (int k = 0; k < H_DIM; k++) {
        float hv = __ldg(hr + k);
        const float* wr = W2s + k * C_DIM;
        a0 += hv * wr[lane];
        a1 += hv * wr[lane + 32];
        if (lane < C_DIM - 64) a2 += hv * wr[lane + 64];
    }
    float* zr = g_z + (size_t)n * C_DIM;
    zr[lane]      = a0;
    zr[lane + 32] = a1;
    if (lane < C_DIM - 64) zr[lane + 64] = a2;
}

// ---------------------------------------------------------------------------
// layer-2 pull aggregation + bias + softmax -> out
// ---------------------------------------------------------------------------
__global__ __launch_bounds__(256) void k_agg2(const float* __restrict__ b2,
                                              float* __restrict__ out) {
    int warp = threadIdx.x >> 5, lane = threadIdx.x & 31;
    int n = blockIdx.x * 8 + warp;
    if (n >= N_NODES) return;
    const bool xtra = lane < 3;

    float dv = g_dinv[n];
    float self = dv * dv;
    const float* zn = g_z + (size_t)n * C_DIM;
    float2 a = *reinterpret_cast<const float2*>(zn + 2 * lane);
    a.x *= self; a.y *= self;
    float2 bacc = make_float2(0.f, 0.f);
    if (xtra) {
        float2 t = *reinterpret_cast<const float2*>(zn + 64 + 2 * lane);
        bacc.x = t.x * self; bacc.y = t.y * self;
    }

    int j  = g_ptr[n];
    int p1 = g_ptr[n + 1];
    int2 en;
    if (j < p1) en = __ldg(&g_csr[j]);
    while (j < p1) {
        int2 cur = en;
        if (j + 1 < p1) en = __ldg(&g_csr[j + 1]);
        float nrm = __int_as_float(cur.y);
        const float* zs = g_z + (size_t)cur.x * C_DIM;
        float2 v = __ldg(reinterpret_cast<const float2*>(zs + 2 * lane));
        a.x += v.x * nrm; a.y += v.y * nrm;
        if (xtra) {
            float2 t = __ldg(reinterpret_cast<const float2*>(zs + 64 + 2 * lane));
            bacc.x += t.x * nrm; bacc.y += t.y * nrm;
        }
        ++j;
    }

    a.x += b2[2 * lane]; a.y += b2[2 * lane + 1];
    if (xtra) { bacc.x += b2[64 + 2 * lane]; bacc.y += b2[65 + 2 * lane]; }

    float m = fmaxf(a.x, a.y);
    if (xtra) m = fmaxf(m, fmaxf(bacc.x, bacc.y));
#pragma unroll
    for (int o = 16; o > 0; o >>= 1) m = fmaxf(m, __shfl_xor_sync(0xffffffff, m, o));

    float e0 = expf(a.x - m), e1 = expf(a.y - m);
    float e2 = 0.f, e3 = 0.f;
    if (xtra) { e2 = expf(bacc.x - m); e3 = expf(bacc.y - m); }
    float s = e0 + e1 + e2 + e3;
#pragma unroll
    for (int o = 16; o > 0; o >>= 1) s += __shfl_xor_sync(0xffffffff, s, o);
    float inv = 1.f / s;

    float* orow = out + (size_t)n * C_DIM;
    *reinterpret_cast<float2*>(orow + 2 * lane) = make_float2(e0 * inv, e1 * inv);
    if (xtra)
        *reinterpret_cast<float2*>(orow + 64 + 2 * lane) =
            make_float2(e2 * inv, e3 * inv);
}

// ---------------------------------------------------------------------------
extern "C" void kernel_launch(void* const* d_in, const int* in_sizes, int n_in,
                              void* d_out, int out_size) {
    const float* x  = (const float*)d_in[0];
    const int* edges = (const int*)d_in[1];
    const float* W1 = (const float*)d_in[2];
    const float* b1 = (const float*)d_in[3];
    const float* W2 = (const float*)d_in[4];
    const float* b2 = (const float*)d_in[5];
    float* out = (float*)d_out;
    const int E = in_sizes[1] / 2;

    cudaFuncSetAttribute(k_gemm1_tc, cudaFuncAttributeMaxDynamicSharedMemorySize,
                         G1_SMEM_BYTES);

    // degree / dinv / CSR / weight prep
    k_zero_deg<<<(N_NODES + 255) / 256, 256>>>();
    k_count_deg<<<(E + 255) / 256, 256>>>(edges, E);
    k_dinv<<<(N_NODES + 255) / 256, 256>>>();
    k_scan1<<<SCAN_G, SCAN_B>>>();
    k_scan2<<<1, 128>>>();
    k_scan3<<<SCAN_G, SCAN_B>>>();
    k_fill<<<(E + 255) / 256, 256>>>(edges, E);
    k_round_w<<<(K_IN * H_DIM + 255) / 256, 256>>>(W1);
    k_zero_tail<<<((N_NODES - SPLIT_ROW0) * 32 + 255) / 256, 256>>>();

    // layer 1: 148 full tiles + 9 tiles split-K x16 = 292 CTAs (one wave)
    k_gemm1_tc<<<N_FULL + (157 - N_FULL) * N_SPLITS, 256, G1_SMEM_BYTES>>>(x);
    k_agg1<<<(N_NODES + 7) / 8, 256>>>(b1);

    // layer 2
    k_gemm2<<<(N_NODES + 7) / 8, 256>>>(W2);
    k_agg2<<<(N_NODES + 7) / 8, 256>>>(b2, out);
}

// round 14
// speedup vs baseline: 1.1572x; 1.0061x over previous
#include <cuda_runtime.h>
#include <math.h>
#include <stdint.h>

#define N_NODES 20000
#define K_IN    8710
#define H_DIM   128
#define C_DIM   70
#define E_MAX   640000

// ---- scratch (static device globals; no allocation allowed) ----
__device__ float g_h[(size_t)N_NODES * H_DIM];    // x@W1 (raw, pre-bias)
__device__ float g_h1[(size_t)N_NODES * H_DIM];   // relu(agg1 + b1)
__device__ float g_z[(size_t)N_NODES * C_DIM];    // h1@W2
__device__ float g_Wr[(size_t)K_IN * H_DIM];      // W1 pre-rounded to tf32
__device__ int   g_deg[N_NODES];
__device__ float g_dinv[N_NODES];
__device__ int   g_ptr[N_NODES + 1];              // CSR row ptr (by dst)
__device__ int   g_cur[N_NODES];                  // fill cursors
__device__ int2  g_csr[E_MAX];                    // {src, bitcast(norm)}
#define SCAN_B 256
#define SCAN_G ((N_NODES + SCAN_B - 1) / SCAN_B)  // 79
__device__ int   g_bsum[SCAN_G];
__device__ int   g_boff[SCAN_G];

// ---------------------------------------------------------------------------
// degree / normalization / CSR build
// ---------------------------------------------------------------------------
__global__ void k_zero_deg() {
    int i = blockIdx.x * blockDim.x + threadIdx.x;
    if (i < N_NODES) g_deg[i] = 0;
}

__global__ void k_count_deg(const int* __restrict__ edges, int E) {
    int e = blockIdx.x * blockDim.x + threadIdx.x;
    if (e < E) atomicAdd(&g_deg[edges[E + e]], 1);   // dst
}

__global__ void k_dinv() {
    int i = blockIdx.x * blockDim.x + threadIdx.x;
    if (i < N_NODES) g_dinv[i] = rsqrtf((float)(g_deg[i] + 1));  // +1 self loop
}

// scan stage 1: per-block sum of degrees
__global__ __launch_bounds__(SCAN_B) void k_scan1() {
    __shared__ int ws[SCAN_B / 32];
    int i = blockIdx.x * SCAN_B + threadIdx.x;
    int v = (i < N_NODES) ? g_deg[i] : 0;
#pragma unroll
    for (int o = 16; o > 0; o >>= 1) v += __shfl_xor_sync(0xffffffff, v, o);
    if ((threadIdx.x & 31) == 0) ws[threadIdx.x >> 5] = v;
    __syncthreads();
    if (threadIdx.x < SCAN_B / 32) {
        int s = ws[threadIdx.x];
#pragma unroll
        for (int o = SCAN_B / 64; o > 0; o >>= 1)
            s += __shfl_xor_sync(0xffffffff, s, o, SCAN_B / 32);
        if (threadIdx.x == 0) g_bsum[blockIdx.x] = s;
    }
}

// scan stage 2: exclusive scan of the 79 block sums (1 block)
__global__ __launch_bounds__(128) void k_scan2() {
    __shared__ int sh[SCAN_G];
    int t = threadIdx.x;
    if (t < SCAN_G) sh[t] = g_bsum[t];
    __syncthreads();
    if (t == 0) {
        int run = 0;
        for (int b = 0; b < SCAN_G; b++) { g_boff[b] = run; run += sh[b]; }
        g_ptr[N_NODES] = run;
    }
}

// scan stage 3: per-block exclusive scan + offset -> g_ptr / g_cur
__global__ __launch_bounds__(SCAN_B) void k_scan3() {
    __shared__ int sh[SCAN_B];
    int i = blockIdx.x * SCAN_B + threadIdx.x;
    int v = (i < N_NODES) ? g_deg[i] : 0;
    sh[threadIdx.x] = v;
    __syncthreads();
    for (int o = 1; o < SCAN_B; o <<= 1) {
        int t = (threadIdx.x >= o) ? sh[threadIdx.x - o] : 0;
        __syncthreads();
        sh[threadIdx.x] += t;
        __syncthreads();
    }
    if (i < N_NODES) {
        int excl = sh[threadIdx.x] - v + g_boff[blockIdx.x];
        g_ptr[i] = excl;
        g_cur[i] = excl;
    }
}

__global__ void k_fill(const int* __restrict__ edges, int E) {
    int e = blockIdx.x * blockDim.x + threadIdx.x;
    if (e >= E) return;
    int s = edges[e];
    int d = edges[E + e];
    int pos = atomicAdd(&g_cur[d], 1);
    g_csr[pos] = make_int2(s, __float_as_int(g_dinv[s] * g_dinv[d]));
}

// ---------------------------------------------------------------------------
// pre-round W1 to tf32 (rna) so GEMM needs no in-loop cvt for B
// ---------------------------------------------------------------------------
__global__ void k_round_w(const float* __restrict__ W1) {
    int i = blockIdx.x * blockDim.x + threadIdx.x;
    if (i < K_IN * H_DIM) {
        unsigned u;
        asm("cvt.rna.tf32.f32 %0, %1;" : "=r"(u) : "f"(W1[i]));
        g_Wr[i] = __uint_as_float(u);
    }
}

// ---------------------------------------------------------------------------
// zero-init g_h rows of the split-K tiles (rows 18944..19999)
// ---------------------------------------------------------------------------
#define SPLIT_ROW0 18944
__global__ void k_zero_tail() {
    int idx = blockIdx.x * blockDim.x + threadIdx.x;   // float4 slots
    int total = (N_NODES - SPLIT_ROW0) * 32;
    if (idx >= total) return;
    *reinterpret_cast<float4*>(g_h + (size_t)SPLIT_ROW0 * H_DIM + idx * 4) =
        make_float4(0.f, 0.f, 0.f, 0.f);
}

// ---------------------------------------------------------------------------
// GEMM1, tf32 HMMA + cp.async 4-stage pipeline.
// R13 base, two edits: (1) A fragments via ldmatrix.x4 (RS=20 conflict-free),
// (2) two chunks per barrier (one commit group per stage-pair, wait_group 0).
//   bid 0..147   : full tiles, chunks [0,545), direct-store epilogue
//   bid 148..291 : tiles 148..156 split-K x16, red.add epilogue
// BM=128, BN=128, BK=16, 256 threads = 8 warps (4m x 2n), warp tile 32x64
// ---------------------------------------------------------------------------
#define NC_CHUNKS ((K_IN + 15) / 16)   // 545
#define G1_STAGES 4
#define G1_BM 128
#define G1_BK 16
#define N_FULL    148
#define N_SPLITS  16
#define A_STRIDE 20
#define B_STRIDE 136
#define A_WORDS (G1_BM * A_STRIDE)                   // 2560
#define STAGE_WORDS (A_WORDS + G1_BK * B_STRIDE)     // 4736
#define STAGE_BYTES_ (STAGE_WORDS * 4)
#define G1_SMEM_BYTES (G1_STAGES * STAGE_WORDS * 4)  // 75776
#define TRUNC_COMP 1.00034f

__device__ __forceinline__ unsigned smem_u32(const void* p) {
    unsigned a;
    asm("{ .reg .u64 t; cvta.to.shared.u64 t, %1; cvt.u32.u64 %0, t; }"
        : "=r"(a) : "l"(p));
    return a;
}

__global__ __launch_bounds__(256, 2) void k_gemm1_tc(const float* __restrict__ X) {
    extern __shared__ float sm[];

    const int tid  = threadIdx.x;
    const int warp = tid >> 5;
    const int lane = tid & 31;
    const int gid  = lane >> 2;
    const int tig  = lane & 3;
    const int warp_m = warp >> 1;
    const int warp_n = warp & 1;
    const unsigned sm_base = smem_u32(sm);

    int tile, c0, c_end;
    bool direct;
    if (blockIdx.x < N_FULL) {
        tile = blockIdx.x; c0 = 0; c_end = NC_CHUNKS; direct = true;
    } else {
        int t = blockIdx.x - N_FULL;
        tile = N_FULL + t / N_SPLITS;
        int s = t % N_SPLITS;
        const int base = NC_CHUNKS / N_SPLITS;
        const int rem  = NC_CHUNKS % N_SPLITS;
        c0    = s * base + (s < rem ? s : rem);
        c_end = c0 + base + (s < rem ? 1 : 0);
        direct = false;
    }
    const int m0 = tile * G1_BM;

    // ldmatrix per-lane A address offset (bytes within a stage):
    // matrices: j0 rows 0-7 k0-3 | j1 rows 8-15 k0-3 | j2 rows 0-7 k4-7 | j3 rows 8-15 k4-7
    const unsigned a_lane_off =
        (unsigned)((warp_m * 32 + ((lane >> 3) & 1) * 8 + (lane & 7)) * (A_STRIDE * 4)
                   + (lane >> 4) * 16);

    float acc[2][8][4];
#pragma unroll
    for (int i = 0; i < 2; i++)
#pragma unroll
        for (int j = 0; j < 8; j++)
#pragma unroll
            for (int t = 0; t < 4; t++) acc[i][j][t] = 0.f;

// stage loader (no commit; caller commits per pair)
#define LOAD_STAGE(c)                                                             \
    {                                                                             \
        const int stg = (c) % G1_STAGES;                                          \
        const unsigned a_u = sm_base + stg * STAGE_BYTES_;                        \
        const unsigned b_u = a_u + A_WORDS * 4;                                   \
        const int k0 = (c) * G1_BK;                                               \
        const bool inr = (c) < c_end;                                             \
        _Pragma("unroll")                                                         \
        for (int i = 0; i < 4; i++) {                                             \
            int p = tid + i * 256;                                                \
            int row = p >> 3;                                                     \
            int kp  = (p & 7) * 2;                                                \
            int gm = m0 + row, gk = k0 + kp;                                      \
            int ok = (inr && gm < N_NODES && gk + 1 < K_IN) ? 8 : 0;              \
            int gmc = gm < N_NODES ? gm : N_NODES - 1;                            \
            int gkc = gk + 1 < K_IN ? gk : 0;                                     \
            const float* src = X + (size_t)gmc * K_IN + gkc;                      \
            unsigned dst = a_u + (row * A_STRIDE + kp) * 4;                       \
            asm volatile("cp.async.ca.shared.global [%0], [%1], 8, %2;"           \
                         :: "r"(dst), "l"(src), "r"(ok));                         \
        }                                                                         \
        _Pragma("unroll")                                                         \
        for (int i = 0; i < 2; i++) {                                             \
            int q = tid + i * 256;                                                \
            int kr = q >> 5;                                                      \
            int nc = (q & 31) * 4;                                                \
            int gk = k0 + kr;                                                     \
            int ok = (inr && gk < K_IN) ? 16 : 0;                                 \
            int gkc = gk < K_IN ? gk : 0;                                         \
            const float* src = g_Wr + (size_t)gkc * H_DIM + nc;                   \
            unsigned dst = b_u + (kr * B_STRIDE + nc) * 4;                        \
            asm volatile("cp.async.cg.shared.global [%0], [%1], 16, %2;"          \
                         :: "r"(dst), "l"(src), "r"(ok));                         \
        }                                                                         \
    }

#define LOAD_PAIR(cc)                                                             \
    {                                                                             \
        LOAD_STAGE(cc);                                                           \
        LOAD_STAGE((cc) + 1);                                                     \
        asm volatile("cp.async.commit_group;");                                   \
    }

#define COMPUTE_CHUNK(c)                                                          \
    {                                                                             \
        const unsigned sa = sm_base + (unsigned)((c) % G1_STAGES) * STAGE_BYTES_; \
        const unsigned* Bs = reinterpret_cast<const unsigned*>(sm)                \
                             + ((c) % G1_STAGES) * STAGE_WORDS + A_WORDS;         \
        _Pragma("unroll")                                                         \
        for (int ks = 0; ks < 2; ks++) {                                          \
            const int kb = ks * 8;                                                \
            unsigned af[2][4];                                                    \
            _Pragma("unroll")                                                     \
            for (int mt = 0; mt < 2; mt++) {                                      \
                asm volatile(                                                     \
                    "ldmatrix.sync.aligned.m8n8.x4.shared.b16 "                   \
                    "{%0,%1,%2,%3}, [%4];"                                        \
                    : "=r"(af[mt][0]), "=r"(af[mt][1]),                           \
                      "=r"(af[mt][2]), "=r"(af[mt][3])                            \
                    : "r"(sa + a_lane_off + mt * (16 * A_STRIDE * 4) + kb * 4));  \
            }                                                                     \
            unsigned bf[8][2];                                                    \
            _Pragma("unroll")                                                     \
            for (int nt = 0; nt < 8; nt++) {                                      \
                int nb = warp_n * 64 + nt * 8 + gid;                              \
                bf[nt][0] = Bs[(kb + tig) * B_STRIDE + nb];                       \
                bf[nt][1] = Bs[(kb + tig + 4) * B_STRIDE + nb];                   \
            }                                                                     \
            _Pragma("unroll")                                                     \
            for (int mt = 0; mt < 2; mt++)                                        \
                _Pragma("unroll")                                                 \
                for (int nt = 0; nt < 8; nt++) {                                  \
                    asm volatile(                                                 \
                        "mma.sync.aligned.m16n8k8.row.col.f32.tf32.tf32.f32 "     \
                        "{%0,%1,%2,%3}, {%4,%5,%6,%7}, {%8,%9}, {%0,%1,%2,%3};"   \
                        : "+f"(acc[mt][nt][0]), "+f"(acc[mt][nt][1]),             \
                          "+f"(acc[mt][nt][2]), "+f"(acc[mt][nt][3])              \
                        : "r"(af[mt][0]), "r"(af[mt][1]),                         \
                          "r"(af[mt][2]), "r"(af[mt][3]),                         \
                          "r"(bf[nt][0]), "r"(bf[nt][1]));                        \
                }                                                                 \
        }                                                                         \
    }

    LOAD_PAIR(c0);

    for (int c = c0; c < c_end; c += 2) {
        asm volatile("cp.async.wait_group 0;");
        __syncthreads();

        LOAD_PAIR(c + 2);   // overwrites stages of c-2, c-1 (done last iter)

        COMPUTE_CHUNK(c);
        if (c + 1 < c_end) COMPUTE_CHUNK(c + 1);
    }
#undef LOAD_STAGE
#undef LOAD_PAIR
#undef COMPUTE_CHUNK

    // epilogue: truncation compensation, write h only (agg is pulled later)
#pragma unroll
    for (int mt = 0; mt < 2; mt++) {
        int r0 = m0 + warp_m * 32 + mt * 16 + gid;
        int r1 = r0 + 8;
#pragma unroll
        for (int nt = 0; nt < 8; nt++) {
            int col = warp_n * 64 + nt * 8 + tig * 2;
            float h0 = acc[mt][nt][0] * TRUNC_COMP;
            float h1 = acc[mt][nt][1] * TRUNC_COMP;
            float h2 = acc[mt][nt][2] * TRUNC_COMP;
            float h3 = acc[mt][nt][3] * TRUNC_COMP;
            if (direct) {
                if (r0 < N_NODES)
                    *reinterpret_cast<float2*>(g_h + (size_t)r0 * H_DIM + col) =
                        make_float2(h0, h1);
                if (r1 < N_NODES)
                    *reinterpret_cast<float2*>(g_h + (size_t)r1 * H_DIM + col) =
                        make_float2(h2, h3);
            } else {
                if (r0 < N_NODES)
                    asm volatile("red.global.add.v2.f32 [%0], {%1,%2};"
                                 :: "l"(g_h + (size_t)r0 * H_DIM + col),
                                    "f"(h0), "f"(h1) : "memory");
                if (r1 < N_NODES)
                    asm volatile("red.global.add.v2.f32 [%0], {%1,%2};"
                                 :: "l"(g_h + (size_t)r1 * H_DIM + col),
                                    "f"(h2), "f"(h3) : "memory");
            }
        }
    }
}

// ---------------------------------------------------------------------------
// layer-1 pull aggregation: h1[n] = relu(b1 + dinv^2*h[n] + sum norm*h[src])
// ---------------------------------------------------------------------------
__global__ __launch_bounds__(256) void k_agg1(const float* __restrict__ b1) {
    int warp = threadIdx.x >> 5, lane = threadIdx.x & 31;
    int n = blockIdx.x * 8 + warp;
    if (n >= N_NODES) return;

    float dv = g_dinv[n];
    float self = dv * dv;
    const float4* hn = reinterpret_cast<const float4*>(g_h + (size_t)n * H_DIM);
    float4 v = __ldg(hn + lane);
    float4 acc = make_float4(v.x * self, v.y * self, v.z * self, v.w * self);

    int j  = g_ptr[n];
    int p1 = g_ptr[n + 1];
    int2 en;
    if (j < p1) en = __ldg(&g_csr[j]);
    while (j < p1) {
        int2 cur = en;
        if (j + 1 < p1) en = __ldg(&g_csr[j + 1]);
        float nrm = __int_as_float(cur.y);
        float4 w = __ldg(reinterpret_cast<const float4*>(
                             g_h + (size_t)cur.x * H_DIM) + lane);
        acc.x += w.x * nrm; acc.y += w.y * nrm;
        acc.z += w.z * nrm; acc.w += w.w * nrm;
        ++j;
    }

    float4 b = __ldg(reinterpret_cast<const float4*>(b1) + lane);
    acc.x = fmaxf(acc.x + b.x, 0.f);
    acc.y = fmaxf(acc.y + b.y, 0.f);
    acc.z = fmaxf(acc.z + b.z, 0.f);
    acc.w = fmaxf(acc.w + b.w, 0.f);
    reinterpret_cast<float4*>(g_h1 + (size_t)n * H_DIM)[lane] = acc;
}

// ---------------------------------------------------------------------------
// GEMM2: z = h1 @ W2   [20000 x 128] @ [128 x 70] — warp per row
// ---------------------------------------------------------------------------
__global__ __launch_bounds__(256) void k_gemm2(const float* __restrict__ W2) {
    __shared__ float W2s[H_DIM * C_DIM];
    int tid = threadIdx.x;
    for (int i = tid; i < H_DIM * C_DIM; i += 256) W2s[i] = W2[i];
    __syncthreads();

    int warp = tid >> 5, lane = tid & 31;
    int n = blockIdx.x * 8 + warp;
    if (n >= N_NODES) return;
    const float* hr = g_h1 + (size_t)n * H_DIM;

    float a0 = 0.f, a1 = 0.f, a2 = 0.f;
#pragma unroll 4
    for (int k = 0; k < H_DIM; k++) {
        float hv = __ldg(hr + k);
        const float* wr = W2s + k * C_DIM;
        a0 += hv * wr[lane];
        a1 += hv * wr[lane + 32];
        if (lane < C_DIM - 64) a2 += hv * wr[lane + 64];
    }
    float* zr = g_z + (size_t)n * C_DIM;
    zr[lane]      = a0;
    zr[lane + 32] = a1;
    if (lane < C_DIM - 64) zr[lane + 64] = a2;
}

// ---------------------------------------------------------------------------
// layer-2 pull aggregation + bias + softmax -> out
// ---------------------------------------------------------------------------
__global__ __launch_bounds__(256) void k_agg2(const float* __restrict__ b2,
                                              float* __restrict__ out) {
    int warp = threadIdx.x >> 5, lane = threadIdx.x & 31;
    int n = blockIdx.x * 8 + warp;
    if (n >= N_NODES) return;
    const bool xtra = lane < 3;

    float dv = g_dinv[n];
    float self = dv * dv;
    const float* zn = g_z + (size_t)n * C_DIM;
    float2 a = *reinterpret_cast<const float2*>(zn + 2 * lane);
    a.x *= self; a.y *= self;
    float2 bacc = make_float2(0.f, 0.f);
    if (xtra) {
        float2 t = *reinterpret_cast<const float2*>(zn + 64 + 2 * lane);
        bacc.x = t.x * self; bacc.y = t.y * self;
    }

    int j  = g_ptr[n];
    int p1 = g_ptr[n + 1];
    int2 en;
    if (j < p1) en = __ldg(&g_csr[j]);
    while (j < p1) {
        int2 cur = en;
        if (j + 1 < p1) en = __ldg(&g_csr[j + 1]);
        float nrm = __int_as_float(cur.y);
        const float* zs = g_z + (size_t)cur.x * C_DIM;
        float2 v = __ldg(reinterpret_cast<const float2*>(zs + 2 * lane));
        a.x += v.x * nrm; a.y += v.y * nrm;
        if (xtra) {
            float2 t = __ldg(reinterpret_cast<const float2*>(zs + 64 + 2 * lane));
            bacc.x += t.x * nrm; bacc.y += t.y * nrm;
        }
        ++j;
    }

    a.x += b2[2 * lane]; a.y += b2[2 * lane + 1];
    if (xtra) { bacc.x += b2[64 + 2 * lane]; bacc.y += b2[65 + 2 * lane]; }

    float m = fmaxf(a.x, a.y);
    if (xtra) m = fmaxf(m, fmaxf(bacc.x, bacc.y));
#pragma unroll
    for (int o = 16; o > 0; o >>= 1) m = fmaxf(m, __shfl_xor_sync(0xffffffff, m, o));

    float e0 = expf(a.x - m), e1 = expf(a.y - m);
    float e2 = 0.f, e3 = 0.f;
    if (xtra) { e2 = expf(bacc.x - m); e3 = expf(bacc.y - m); }
    float s = e0 + e1 + e2 + e3;
#pragma unroll
    for (int o = 16; o > 0; o >>= 1) s += __shfl_xor_sync(0xffffffff, s, o);
    float inv = 1.f / s;

    float* orow = out + (size_t)n * C_DIM;
    *reinterpret_cast<float2*>(orow + 2 * lane) = make_float2(e0 * inv, e1 * inv);
    if (xtra)
        *reinterpret_cast<float2*>(orow + 64 + 2 * lane) =
            make_float2(e2 * inv, e3 * inv);
}

// ---------------------------------------------------------------------------
extern "C" void kernel_launch(void* const* d_in, const int* in_sizes, int n_in,
                              void* d_out, int out_size) {
    const float* x  = (const float*)d_in[0];
    const int* edges = (const int*)d_in[1];
    const float* W1 = (const float*)d_in[2];
    const float* b1 = (const float*)d_in[3];
    const float* W2 = (const float*)d_in[4];
    const float* b2 = (const float*)d_in[5];
    float* out = (float*)d_out;
    const int E = in_sizes[1] / 2;

    cudaFuncSetAttribute(k_gemm1_tc, cudaFuncAttributeMaxDynamicSharedMemorySize,
                         G1_SMEM_BYTES);

    // degree / dinv / CSR / weight prep
    k_zero_deg<<<(N_NODES + 255) / 256, 256>>>();
    k_count_deg<<<(E + 255) / 256, 256>>>(edges, E);
    k_dinv<<<(N_NODES + 255) / 256, 256>>>();
    k_scan1<<<SCAN_G, SCAN_B>>>();
    k_scan2<<<1, 128>>>();
    k_scan3<<<SCAN_G, SCAN_B>>>();
    k_fill<<<(E + 255) / 256, 256>>>(edges, E);
    k_round_w<<<(K_IN * H_DIM + 255) / 256, 256>>>(W1);
    k_zero_tail<<<((N_NODES - SPLIT_ROW0) * 32 + 255) / 256, 256>>>();

    // layer 1: 148 full tiles + 9 tiles split-K x16 = 292 CTAs (one wave)
    k_gemm1_tc<<<N_FULL + (157 - N_FULL) * N_SPLITS, 256, G1_SMEM_BYTES>>>(x);
    k_agg1<<<(N_NODES + 7) / 8, 256>>>(b1);

    // layer 2
    k_gemm2<<<(N_NODES + 7) / 8, 256>>>(W2);
    k_agg2<<<(N_NODES + 7) / 8, 256>>>(b2, out);
}

// round 15
// speedup vs baseline: 1.2561x; 1.0855x over previous
#include <cuda_runtime.h>
#include <cuda_fp16.h>
#include <math.h>
#include <stdint.h>

#define N_NODES 20000
#define K_IN    8710
#define H_DIM   128
#define C_DIM   70
#define E_MAX   640000

// ---- scratch (static device globals; no allocation allowed) ----
__device__ float g_h[(size_t)N_NODES * H_DIM];    // x@W1 (raw, pre-bias)
__device__ float g_h1[(size_t)N_NODES * H_DIM];   // relu(agg1 + b1)
__device__ float g_z[(size_t)N_NODES * C_DIM];    // h1@W2
__device__ __align__(16) __half g_Wh[(size_t)K_IN * H_DIM];  // W1 in fp16
__device__ int   g_deg[N_NODES];
__device__ float g_dinv[N_NODES];
__device__ int   g_ptr[N_NODES + 1];              // CSR row ptr (by dst)
__device__ int   g_cur[N_NODES];                  // fill cursors
__device__ int2  g_csr[E_MAX];                    // {src, bitcast(norm)}
#define SCAN_B 256
#define SCAN_G ((N_NODES + SCAN_B - 1) / SCAN_B)  // 79
__device__ int   g_bsum[SCAN_G];
__device__ int   g_boff[SCAN_G];

// ---------------------------------------------------------------------------
// degree / normalization / CSR build
// ---------------------------------------------------------------------------
__global__ void k_zero_deg() {
    int i = blockIdx.x * blockDim.x + threadIdx.x;
    if (i < N_NODES) g_deg[i] = 0;
}

__global__ void k_count_deg(const int* __restrict__ edges, int E) {
    int e = blockIdx.x * blockDim.x + threadIdx.x;
    if (e < E) atomicAdd(&g_deg[edges[E + e]], 1);   // dst
}

__global__ void k_dinv() {
    int i = blockIdx.x * blockDim.x + threadIdx.x;
    if (i < N_NODES) g_dinv[i] = rsqrtf((float)(g_deg[i] + 1));  // +1 self loop
}

// scan stage 1: per-block sum of degrees
__global__ __launch_bounds__(SCAN_B) void k_scan1() {
    __shared__ int ws[SCAN_B / 32];
    int i = blockIdx.x * SCAN_B + threadIdx.x;
    int v = (i < N_NODES) ? g_deg[i] : 0;
#pragma unroll
    for (int o = 16; o > 0; o >>= 1) v += __shfl_xor_sync(0xffffffff, v, o);
    if ((threadIdx.x & 31) == 0) ws[threadIdx.x >> 5] = v;
    __syncthreads();
    if (threadIdx.x < SCAN_B / 32) {
        int s = ws[threadIdx.x];
#pragma unroll
        for (int o = SCAN_B / 64; o > 0; o >>= 1)
            s += __shfl_xor_sync(0xffffffff, s, o, SCAN_B / 32);
        if (threadIdx.x == 0) g_bsum[blockIdx.x] = s;
    }
}

// scan stage 2: exclusive scan of the 79 block sums (1 block)
__global__ __launch_bounds__(128) void k_scan2() {
    __shared__ int sh[SCAN_G];
    int t = threadIdx.x;
    if (t < SCAN_G) sh[t] = g_bsum[t];
    __syncthreads();
    if (t == 0) {
        int run = 0;
        for (int b = 0; b < SCAN_G; b++) { g_boff[b] = run; run += sh[b]; }
        g_ptr[N_NODES] = run;
    }
}

// scan stage 3: per-block exclusive scan + offset -> g_ptr / g_cur
__global__ __launch_bounds__(SCAN_B) void k_scan3() {
    __shared__ int sh[SCAN_B];
    int i = blockIdx.x * SCAN_B + threadIdx.x;
    int v = (i < N_NODES) ? g_deg[i] : 0;
    sh[threadIdx.x] = v;
    __syncthreads();
    for (int o = 1; o < SCAN_B; o <<= 1) {
        int t = (threadIdx.x >= o) ? sh[threadIdx.x - o] : 0;
        __syncthreads();
        sh[threadIdx.x] += t;
        __syncthreads();
    }
    if (i < N_NODES) {
        int excl = sh[threadIdx.x] - v + g_boff[blockIdx.x];
        g_ptr[i] = excl;
        g_cur[i] = excl;
    }
}

__global__ void k_fill(const int* __restrict__ edges, int E) {
    int e = blockIdx.x * blockDim.x + threadIdx.x;
    if (e >= E) return;
    int s = edges[e];
    int d = edges[E + e];
    int pos = atomicAdd(&g_cur[d], 1);
    g_csr[pos] = make_int2(s, __float_as_int(g_dinv[s] * g_dinv[d]));
}

// ---------------------------------------------------------------------------
// pre-convert W1 to fp16 (rn)
// ---------------------------------------------------------------------------
__global__ void k_half_w(const float* __restrict__ W1) {
    int i = blockIdx.x * blockDim.x + threadIdx.x;
    if (i < K_IN * H_DIM) g_Wh[i] = __float2half_rn(W1[i]);
}

// ---------------------------------------------------------------------------
// zero-init g_h rows of the split-K tiles (rows 18944..19999)
// ---------------------------------------------------------------------------
#define SPLIT_ROW0 18944
__global__ void k_zero_tail() {
    int idx = blockIdx.x * blockDim.x + threadIdx.x;   // float4 slots
    int total = (N_NODES - SPLIT_ROW0) * 32;
    if (idx >= total) return;
    *reinterpret_cast<float4*>(g_h + (size_t)SPLIT_ROW0 * H_DIM + idx * 4) =
        make_float4(0.f, 0.f, 0.f, 0.f);
}

// ---------------------------------------------------------------------------
// GEMM1: fp16 HMMA m16n8k16, cp.async 4-stage pipeline, pair barriers.
// A fp32 in smem (cvt to fp16 in registers); B fp16 in smem (ldmatrix.trans).
//   bid 0..147   : full tiles, chunks [0,545), direct-store epilogue
//   bid 148..291 : tiles 148..156 split-K x16, red.add epilogue
// BM=128, BN=128, BK=16, 256 threads = 8 warps (4m x 2n), warp tile 32x64
// ---------------------------------------------------------------------------
#define NC_CHUNKS ((K_IN + 15) / 16)   // 545
#define G1_STAGES 4
#define G1_BM 128
#define G1_BK 16
#define N_FULL    148
#define N_SPLITS  16
#define A_STRIDE 20                      // fp32 words per A row (pad)
#define A_WORDS (G1_BM * A_STRIDE)       // 2560
#define A_BYTES (A_WORDS * 4)            // 10240
#define B_ROW_BYTES 272                  // 128 halves + 8 pad halves
#define B_BYTES (G1_BK * B_ROW_BYTES)    // 4352
#define STAGE_BYTES_ (A_BYTES + B_BYTES) // 14592
#define STAGE_WORDS (STAGE_BYTES_ / 4)   // 3648
#define G1_SMEM_BYTES (G1_STAGES * STAGE_BYTES_)  // 58368

__device__ __forceinline__ unsigned smem_u32(const void* p) {
    unsigned a;
    asm("{ .reg .u64 t; cvta.to.shared.u64 t, %1; cvt.u32.u64 %0, t; }"
        : "=r"(a) : "l"(p));
    return a;
}

__device__ __forceinline__ unsigned pack_f16x2(float hi, float lo) {
    unsigned d;
    asm("cvt.rn.f16x2.f32 %0, %1, %2;" : "=r"(d) : "f"(hi), "f"(lo));
    return d;
}

__global__ __launch_bounds__(256, 2) void k_gemm1_tc(const float* __restrict__ X) {
    extern __shared__ float sm[];

    const int tid  = threadIdx.x;
    const int warp = tid >> 5;
    const int lane = tid & 31;
    const int gid  = lane >> 2;
    const int tig  = lane & 3;
    const int warp_m = warp >> 1;
    const int warp_n = warp & 1;
    const unsigned sm_base = smem_u32(sm);

    int tile, c0, c_end;
    bool direct;
    if (blockIdx.x < N_FULL) {
        tile = blockIdx.x; c0 = 0; c_end = NC_CHUNKS; direct = true;
    } else {
        int t = blockIdx.x - N_FULL;
        tile = N_FULL + t / N_SPLITS;
        int s = t % N_SPLITS;
        const int base = NC_CHUNKS / N_SPLITS;
        const int rem  = NC_CHUNKS % N_SPLITS;
        c0    = s * base + (s < rem ? s : rem);
        c_end = c0 + base + (s < rem ? 1 : 0);
        direct = false;
    }
    const int m0 = tile * G1_BM;

    // per-lane ldmatrix.trans address offset for B (bytes within B region):
    // x4 tiles: t0 = k0-7 @ nb, t1 = k8-15 @ nb, t2 = k0-7 @ nb+8, t3 = k8-15 @ nb+8
    const int tsel = lane >> 3;       // 0..3
    const int jrow = lane & 7;        // 0..7
    const unsigned b_lane_off =
        (unsigned)(((tsel & 1) * 8 + jrow) * B_ROW_BYTES
                   + (warp_n * 64 + (tsel >> 1) * 8) * 2);

    float acc[2][8][4];
#pragma unroll
    for (int i = 0; i < 2; i++)
#pragma unroll
        for (int j = 0; j < 8; j++)
#pragma unroll
            for (int t = 0; t < 4; t++) acc[i][j][t] = 0.f;

// stage loader (no commit; caller commits per pair)
#define LOAD_STAGE(c)                                                             \
    {                                                                             \
        const int stg = (c) % G1_STAGES;                                          \
        const unsigned a_u = sm_base + stg * STAGE_BYTES_;                        \
        const unsigned b_u = a_u + A_BYTES;                                       \
        const int k0 = (c) * G1_BK;                                               \
        const bool inr = (c) < c_end;                                             \
        _Pragma("unroll")                                                         \
        for (int i = 0; i < 4; i++) {                                             \
            int p = tid + i * 256;                                                \
            int row = p >> 3;                                                     \
            int kp  = (p & 7) * 2;                                                \
            int gm = m0 + row, gk = k0 + kp;                                      \
            int ok = (inr && gm < N_NODES && gk + 1 < K_IN) ? 8 : 0;              \
            int gmc = gm < N_NODES ? gm : N_NODES - 1;                            \
            int gkc = gk + 1 < K_IN ? gk : 0;                                     \
            const float* src = X + (size_t)gmc * K_IN + gkc;                      \
            unsigned dst = a_u + (row * A_STRIDE + kp) * 4;                       \
            asm volatile("cp.async.ca.shared.global [%0], [%1], 8, %2;"           \
                         :: "r"(dst), "l"(src), "r"(ok));                         \
        }                                                                         \
        {                                                                         \
            int kr = tid >> 4;              /* 0..15 */                           \
            int nc = (tid & 15) * 8;        /* halves */                          \
            int gk = k0 + kr;                                                     \
            int ok = (inr && gk < K_IN) ? 16 : 0;                                 \
            int gkc = gk < K_IN ? gk : 0;                                         \
            const __half* src = g_Wh + (size_t)gkc * H_DIM + nc;                  \
            unsigned dst = b_u + kr * B_ROW_BYTES + nc * 2;                       \
            asm volatile("cp.async.cg.shared.global [%0], [%1], 16, %2;"          \
                         :: "r"(dst), "l"(src), "r"(ok));                         \
        }                                                                         \
    }

#define LOAD_PAIR(cc)                                                             \
    {                                                                             \
        LOAD_STAGE(cc);                                                           \
        LOAD_STAGE((cc) + 1);                                                     \
        asm volatile("cp.async.commit_group;");                                   \
    }

#define COMPUTE_CHUNK(c)                                                          \
    {                                                                             \
        const float* As = sm + ((c) % G1_STAGES) * STAGE_WORDS;                   \
        const unsigned b_u = sm_base + (unsigned)((c) % G1_STAGES) * STAGE_BYTES_ \
                             + A_BYTES;                                           \
        unsigned af[2][4];                                                        \
        _Pragma("unroll")                                                         \
        for (int mt = 0; mt < 2; mt++) {                                          \
            int r = warp_m * 32 + mt * 16 + gid;                                  \
            const float2* Ap  = reinterpret_cast<const float2*>(                  \
                                    As + r * A_STRIDE);                           \
            const float2* Ap8 = reinterpret_cast<const float2*>(                  \
                                    As + (r + 8) * A_STRIDE);                     \
            float2 v0 = Ap[tig];                                                  \
            float2 v1 = Ap8[tig];                                                 \
            float2 v2 = Ap[tig + 4];                                              \
            float2 v3 = Ap8[tig + 4];                                             \
            af[mt][0] = pack_f16x2(v0.y, v0.x);                                   \
            af[mt][1] = pack_f16x2(v1.y, v1.x);                                   \
            af[mt][2] = pack_f16x2(v2.y, v2.x);                                   \
            af[mt][3] = pack_f16x2(v3.y, v3.x);                                   \
        }                                                                         \
        unsigned bf[8][2];                                                        \
        _Pragma("unroll")                                                         \
        for (int p = 0; p < 4; p++) {                                             \
            asm volatile(                                                         \
                "ldmatrix.sync.aligned.m8n8.x4.trans.shared.b16 "                 \
                "{%0,%1,%2,%3}, [%4];"                                            \
                : "=r"(bf[2 * p][0]), "=r"(bf[2 * p][1]),                         \
                  "=r"(bf[2 * p + 1][0]), "=r"(bf[2 * p + 1][1])                  \
                : "r"(b_u + b_lane_off + p * 32));                                \
        }                                                                         \
        _Pragma("unroll")                                                         \
        for (int mt = 0; mt < 2; mt++)                                            \
            _Pragma("unroll")                                                     \
            for (int nt = 0; nt < 8; nt++) {                                      \
                asm volatile(                                                     \
                    "mma.sync.aligned.m16n8k16.row.col.f32.f16.f16.f32 "          \
                    "{%0,%1,%2,%3}, {%4,%5,%6,%7}, {%8,%9}, {%0,%1,%2,%3};"       \
                    : "+f"(acc[mt][nt][0]), "+f"(acc[mt][nt][1]),                 \
                      "+f"(acc[mt][nt][2]), "+f"(acc[mt][nt][3])                  \
                    : "r"(af[mt][0]), "r"(af[mt][1]),                             \
                      "r"(af[mt][2]), "r"(af[mt][3]),                             \
                      "r"(bf[nt][0]), "r"(bf[nt][1]));                            \
            }                                                                     \
    }

    LOAD_PAIR(c0);

    for (int c = c0; c < c_end; c += 2) {
        asm volatile("cp.async.wait_group 0;");
        __syncthreads();

        LOAD_PAIR(c + 2);   // overwrites stages of c-2, c-1 (done last iter)

        COMPUTE_CHUNK(c);
        if (c + 1 < c_end) COMPUTE_CHUNK(c + 1);
    }
#undef LOAD_STAGE
#undef LOAD_PAIR
#undef COMPUTE_CHUNK

    // epilogue: write h only (agg is pulled later); no trunc compensation (rn cvt)
#pragma unroll
    for (int mt = 0; mt < 2; mt++) {
        int r0 = m0 + warp_m * 32 + mt * 16 + gid;
        int r1 = r0 + 8;
#pragma unroll
        for (int nt = 0; nt < 8; nt++) {
            int col = warp_n * 64 + nt * 8 + tig * 2;
            float h0 = acc[mt][nt][0];
            float h1 = acc[mt][nt][1];
            float h2 = acc[mt][nt][2];
            float h3 = acc[mt][nt][3];
            if (direct) {
                if (r0 < N_NODES)
                    *reinterpret_cast<float2*>(g_h + (size_t)r0 * H_DIM + col) =
                        make_float2(h0, h1);
                if (r1 < N_NODES)
                    *reinterpret_cast<float2*>(g_h + (size_t)r1 * H_DIM + col) =
                        make_float2(h2, h3);
            } else {
                if (r0 < N_NODES)
                    asm volatile("red.global.add.v2.f32 [%0], {%1,%2};"
                                 :: "l"(g_h + (size_t)r0 * H_DIM + col),
                                    "f"(h0), "f"(h1) : "memory");
                if (r1 < N_NODES)
                    asm volatile("red.global.add.v2.f32 [%0], {%1,%2};"
                                 :: "l"(g_h + (size_t)r1 * H_DIM + col),
                                    "f"(h2), "f"(h3) : "memory");
            }
        }
    }
}

// ---------------------------------------------------------------------------
// layer-1 pull aggregation: h1[n] = relu(b1 + dinv^2*h[n] + sum norm*h[src])
// ---------------------------------------------------------------------------
__global__ __launch_bounds__(256) void k_agg1(const float* __restrict__ b1) {
    int warp = threadIdx.x >> 5, lane = threadIdx.x & 31;
    int n = blockIdx.x * 8 + warp;
    if (n >= N_NODES) return;

    float dv = g_dinv[n];
    float self = dv * dv;
    const float4* hn = reinterpret_cast<const float4*>(g_h + (size_t)n * H_DIM);
    float4 v = __ldg(hn + lane);
    float4 acc = make_float4(v.x * self, v.y * self, v.z * self, v.w * self);

    int j  = g_ptr[n];
    int p1 = g_ptr[n + 1];
    int2 en;
    if (j < p1) en = __ldg(&g_csr[j]);
    while (j < p1) {
        int2 cur = en;
        if (j + 1 < p1) en = __ldg(&g_csr[j + 1]);
        float nrm = __int_as_float(cur.y);
        float4 w = __ldg(reinterpret_cast<const float4*>(
                             g_h + (size_t)cur.x * H_DIM) + lane);
        acc.x += w.x * nrm; acc.y += w.y * nrm;
        acc.z += w.z * nrm; acc.w += w.w * nrm;
        ++j;
    }

    float4 b = __ldg(reinterpret_cast<const float4*>(b1) + lane);
    acc.x = fmaxf(acc.x + b.x, 0.f);
    acc.y = fmaxf(acc.y + b.y, 0.f);
    acc.z = fmaxf(acc.z + b.z, 0.f);
    acc.w = fmaxf(acc.w + b.w, 0.f);
    reinterpret_cast<float4*>(g_h1 + (size_t)n * H_DIM)[lane] = acc;
}

// ---------------------------------------------------------------------------
// GEMM2: z = h1 @ W2   [20000 x 128] @ [128 x 70] — warp per row
// ---------------------------------------------------------------------------
__global__ __launch_bounds__(256) void k_gemm2(const float* __restrict__ W2) {
    __shared__ float W2s[H_DIM * C_DIM];
    int tid = threadIdx.x;
    for (int i = tid; i < H_DIM * C_DIM; i += 256) W2s[i] = W2[i];
    __syncthreads();

    int warp = tid >> 5, lane = tid & 31;
    int n = blockIdx.x * 8 + warp;
    if (n >= N_NODES) return;
    const float* hr = g_h1 + (size_t)n * H_DIM;

    float a0 = 0.f, a1 = 0.f, a2 = 0.f;
#pragma unroll 4
    for (int k = 0; k < H_DIM; k++) {
        float hv = __ldg(hr + k);
        const float* wr = W2s + k * C_DIM;
        a0 += hv * wr[lane];
        a1 += hv * wr[lane + 32];
        if (lane < C_DIM - 64) a2 += hv * wr[lane + 64];
    }
    float* zr = g_z + (size_t)n * C_DIM;
    zr[lane]      = a0;
    zr[lane + 32] = a1;
    if (lane < C_DIM - 64) zr[lane + 64] = a2;
}

// ---------------------------------------------------------------------------
// layer-2 pull aggregation + bias + softmax -> out
// ---------------------------------------------------------------------------
__global__ __launch_bounds__(256) void k_agg2(const float* __restrict__ b2,
                                              float* __restrict__ out) {
    int warp = threadIdx.x >> 5, lane = threadIdx.x & 31;
    int n = blockIdx.x * 8 + warp;
    if (n >= N_NODES) return;
    const bool xtra = lane < 3;

    float dv = g_dinv[n];
    float self = dv * dv;
    const float* zn = g_z + (size_t)n * C_DIM;
    float2 a = *reinterpret_cast<const float2*>(zn + 2 * lane);
    a.x *= self; a.y *= self;
    float2 bacc = make_float2(0.f, 0.f);
    if (xtra) {
        float2 t = *reinterpret_cast<const float2*>(zn + 64 + 2 * lane);
        bacc.x = t.x * self; bacc.y = t.y * self;
    }

    int j  = g_ptr[n];
    int p1 = g_ptr[n + 1];
    int2 en;
    if (j < p1) en = __ldg(&g_csr[j]);
    while (j < p1) {
        int2 cur = en;
        if (j + 1 < p1) en = __ldg(&g_csr[j + 1]);
        float nrm = __int_as_float(cur.y);
        const float* zs = g_z + (size_t)cur.x * C_DIM;
        float2 v = __ldg(reinterpret_cast<const float2*>(zs + 2 * lane));
        a.x += v.x * nrm; a.y += v.y * nrm;
        if (xtra) {
            float2 t = __ldg(reinterpret_cast<const float2*>(zs + 64 + 2 * lane));
            bacc.x += t.x * nrm; bacc.y += t.y * nrm;
        }
        ++j;
    }

    a.x += b2[2 * lane]; a.y += b2[2 * lane + 1];
    if (xtra) { bacc.x += b2[64 + 2 * lane]; bacc.y += b2[65 + 2 * lane]; }

    float m = fmaxf(a.x, a.y);
    if (xtra) m = fmaxf(m, fmaxf(bacc.x, bacc.y));
#pragma unroll
    for (int o = 16; o > 0; o >>= 1) m = fmaxf(m, __shfl_xor_sync(0xffffffff, m, o));

    float e0 = expf(a.x - m), e1 = expf(a.y - m);
    float e2 = 0.f, e3 = 0.f;
    if (xtra) { e2 = expf(bacc.x - m); e3 = expf(bacc.y - m); }
    float s = e0 + e1 + e2 + e3;
#pragma unroll
    for (int o = 16; o > 0; o >>= 1) s += __shfl_xor_sync(0xffffffff, s, o);
    float inv = 1.f / s;

    float* orow = out + (size_t)n * C_DIM;
    *reinterpret_cast<float2*>(orow + 2 * lane) = make_float2(e0 * inv, e1 * inv);
    if (xtra)
        *reinterpret_cast<float2*>(orow + 64 + 2 * lane) =
            make_float2(e2 * inv, e3 * inv);
}

// ---------------------------------------------------------------------------
extern "C" void kernel_launch(void* const* d_in, const int* in_sizes, int n_in,
                              void* d_out, int out_size) {
    const float* x  = (const float*)d_in[0];
    const int* edges = (const int*)d_in[1];
    const float* W1 = (const float*)d_in[2];
    const float* b1 = (const float*)d_in[3];
    const float* W2 = (const float*)d_in[4];
    const float* b2 = (const float*)d_in[5];
    float* out = (float*)d_out;
    const int E = in_sizes[1] / 2;

    cudaFuncSetAttribute(k_gemm1_tc, cudaFuncAttributeMaxDynamicSharedMemorySize,
                         G1_SMEM_BYTES);

    // degree / dinv / CSR / weight prep
    k_zero_deg<<<(N_NODES + 255) / 256, 256>>>();
    k_count_deg<<<(E + 255) / 256, 256>>>(edges, E);
    k_dinv<<<(N_NODES + 255) / 256, 256>>>();
    k_scan1<<<SCAN_G, SCAN_B>>>();
    k_scan2<<<1, 128>>>();
    k_scan3<<<SCAN_G, SCAN_B>>>();
    k_fill<<<(E + 255) / 256, 256>>>(edges, E);
    k_half_w<<<(K_IN * H_DIM + 255) / 256, 256>>>(W1);
    k_zero_tail<<<((N_NODES - SPLIT_ROW0) * 32 + 255) / 256, 256>>>();

    // layer 1: 148 full tiles + 9 tiles split-K x16 = 292 CTAs (one wave)
    k_gemm1_tc<<<N_FULL + (157 - N_FULL) * N_SPLITS, 256, G1_SMEM_BYTES>>>(x);
    k_agg1<<<(N_NODES + 7) / 8, 256>>>(b1);

    // layer 2
    k_gemm2<<<(N_NODES + 7) / 8, 256>>>(W2);
    k_agg2<<<(N_NODES + 7) / 8, 256>>>(b2, out);
}